// round 15
// baseline (speedup 1.0000x reference)
#include <cuda_runtime.h>
#include <cstdint>

#define NUM_LAYER_NODES  262144
#define BATCH            128
#define NODES_PER_WARP   4

// R9 core + 256-bit paired stores.
// Loads: for each node, lanes 0-15 load child0's 512B row (32B/lane) and
// lanes 16-31 child1's row in ONE v8.b32 evict_last instruction; shfl.xor(16)
// gives every lane the full child0+child1 sums for its 32B chunk.
// Stores: since BOTH half-warps hold complete sums, nodes are paired — lanes
// 0-15 store node A's row, lanes 16-31 store node B's row, one v8.b32
// evict_first store each -> 2 STG/warp instead of 4. DRAM bytes unchanged.
static __device__ __forceinline__ void ldg256_el(const float* p, float* r) {
    asm volatile("ld.global.nc.L2::evict_last.v8.b32 "
                 "{%0,%1,%2,%3,%4,%5,%6,%7}, [%8];"
                 : "=f"(r[0]), "=f"(r[1]), "=f"(r[2]), "=f"(r[3]),
                   "=f"(r[4]), "=f"(r[5]), "=f"(r[6]), "=f"(r[7])
                 : "l"(p));
}

static __device__ __forceinline__ void stg256_ef(float* p, const float* s) {
    asm volatile("st.global.L2::evict_first.v8.b32 "
                 "[%0], {%1,%2,%3,%4,%5,%6,%7,%8};"
                 :: "l"(p), "f"(s[0]), "f"(s[1]), "f"(s[2]), "f"(s[3]),
                    "f"(s[4]), "f"(s[5]), "f"(s[6]), "f"(s[7])
                 : "memory");
}

__global__ void __launch_bounds__(256)
prod_layer_kernel(const float* __restrict__ node_mars,
                  const float* __restrict__ element_mars,
                  const int* __restrict__ nids,
                  const int* __restrict__ cids,
                  float* __restrict__ out)
{
    const unsigned gwarp = (blockIdx.x * blockDim.x + threadIdx.x) >> 5;
    const unsigned lane  = threadIdx.x & 31;
    const unsigned base  = gwarp * NODES_PER_WARP;

    if (base >= NUM_LAYER_NODES) {
        if (base == NUM_LAYER_NODES) {
            // Reserved row 0: pass through element_mars[0, :] (d_out poisoned).
            const float4* src = reinterpret_cast<const float4*>(element_mars);
            float4* dst = reinterpret_cast<float4*>(out);
            dst[lane] = src[lane];
        }
        return;
    }

    const int4 n4  = __ldg(reinterpret_cast<const int4*>(&nids[base]));
    const int4 c01 = __ldg(reinterpret_cast<const int4*>(&cids[2 * base]));
    const int4 c23 = __ldg(reinterpret_cast<const int4*>(&cids[2 * base + 4]));

    const bool     hi    = lane >= 16;
    const unsigned chunk = (lane & 15) * 8;      // float offset of 32B chunk

    // Per-node child row selected by half-warp (load phase).
    const long long r0 = (long long)(hi ? c01.y : c01.x) * BATCH;
    const long long r1 = (long long)(hi ? c01.w : c01.z) * BATCH;
    const long long r2 = (long long)(hi ? c23.y : c23.x) * BATCH;
    const long long r3 = (long long)(hi ? c23.w : c23.z) * BATCH;

    // Issue all 4 x 256-bit gather loads up front (4KB outstanding/warp).
    float v0[8], v1[8], v2[8], v3[8];
    ldg256_el(node_mars + r0 + chunk, v0);
    ldg256_el(node_mars + r1 + chunk, v1);
    ldg256_el(node_mars + r2 + chunk, v2);
    ldg256_el(node_mars + r3 + chunk, v3);

    // Pairwise child sums; after shfl both half-warps hold full sums.
    float s0[8], s1[8], s2[8], s3[8];
    #pragma unroll
    for (int i = 0; i < 8; i++) {
        s0[i] = v0[i] + __shfl_xor_sync(0xffffffffu, v0[i], 16);
        s1[i] = v1[i] + __shfl_xor_sync(0xffffffffu, v1[i], 16);
        s2[i] = v2[i] + __shfl_xor_sync(0xffffffffu, v2[i], 16);
        s3[i] = v3[i] + __shfl_xor_sync(0xffffffffu, v3[i], 16);
    }

    // Paired 256-bit stores: lanes 0-15 -> nodes x/z, lanes 16-31 -> y/w.
    const long long rowA = (long long)(hi ? n4.y : n4.x) * BATCH;
    const long long rowB = (long long)(hi ? n4.w : n4.z) * BATCH;

    float tA[8], tB[8];
    #pragma unroll
    for (int i = 0; i < 8; i++) {
        tA[i] = hi ? s1[i] : s0[i];
        tB[i] = hi ? s3[i] : s2[i];
    }
    stg256_ef(out + rowA + chunk, tA);
    stg256_ef(out + rowB + chunk, tB);
}

extern "C" void kernel_launch(void* const* d_in, const int* in_sizes, int n_in,
                              void* d_out, int out_size)
{
    const float* node_mars    = (const float*)d_in[0];
    const float* element_mars = (const float*)d_in[1];
    const int*   nids         = (const int*)d_in[2];
    const int*   cids         = (const int*)d_in[3];
    float*       out          = (float*)d_out;

    const unsigned total_warps   = NUM_LAYER_NODES / NODES_PER_WARP + 1;
    const unsigned threads       = 256;               // 8 warps/block
    const unsigned warps_per_blk = threads / 32;
    const unsigned blocks = (total_warps + warps_per_blk - 1) / warps_per_blk;

    prod_layer_kernel<<<blocks, threads>>>(node_mars, element_mars, nids, cids, out);
}